// round 14
// baseline (speedup 1.0000x reference)
#include <cuda_runtime.h>
#include <cuda_bf16.h>
#include <cuda_fp16.h>
#include <cstdint>

#define HID   256
#define HID2  512
#define MAXN  50000
#define MAXE  800000

// Scratch
__device__ __half g_ABh[(size_t)MAXN * HID2];   // fp16 activations (b1 folded)
__device__ __half g_Wt[HID2 * HID];             // [n][k], k-contiguous fp16
__device__ __half g_Z16[(size_t)MAXN * HID];    // z in fp16
__device__ int  g_EI[2 * MAXE];                 // interleaved (src,dst) clamped
__device__ int  g_count[MAXN];                  // histogram
__device__ int  g_off[MAXN];                    // scan offsets (consumed by scatter)
__device__ int4 g_sorted[MAXE];                 // (s, d, orig_e, 0) sorted by s
__device__ int  g_idx64_flag;

// ---------------------------------------------------------------------------
// helpers
// ---------------------------------------------------------------------------
__device__ __forceinline__ uint32_t smem_u32(const void* p) {
    uint32_t a;
    asm("{ .reg .u64 t; cvta.to.shared.u64 t, %1; cvt.u32.u64 %0, t; }"
        : "=r"(a) : "l"(p));
    return a;
}
__device__ __forceinline__ void cp16(uint32_t s, const void* g) {
    asm volatile("cp.async.cg.shared.global [%0], [%1], 16;" :: "r"(s), "l"(g) : "memory");
}
__device__ __forceinline__ void ldsm_x4(uint32_t* r, uint32_t a) {
    asm volatile("ldmatrix.sync.aligned.m8n8.x4.shared.b16 {%0,%1,%2,%3}, [%4];"
                 : "=r"(r[0]), "=r"(r[1]), "=r"(r[2]), "=r"(r[3]) : "r"(a));
}
__device__ __forceinline__ void mma_f16(float* c, const uint32_t* a, const uint32_t* b) {
    asm volatile("mma.sync.aligned.m16n8k16.row.col.f32.f16.f16.f32 "
                 "{%0,%1,%2,%3}, {%4,%5,%6,%7}, {%8,%9}, {%0,%1,%2,%3};"
                 : "+f"(c[0]), "+f"(c[1]), "+f"(c[2]), "+f"(c[3])
                 : "r"(a[0]), "r"(a[1]), "r"(a[2]), "r"(a[3]), "r"(b[0]), "r"(b[1]));
}
__device__ __forceinline__ uint32_t swz(int r, int kb) {
    return ((uint32_t)(r * 128 + kb)) ^ ((uint32_t)(r & 7) << 4);
}

// ---------------------------------------------------------------------------
// Fused preprocessing: split_z + pack_w + zero histogram + probe
// ---------------------------------------------------------------------------
__global__ void preproc_kernel(const float* __restrict__ z,
                               const float* __restrict__ W1,
                               const void* __restrict__ ei,
                               int M, int E) {
    int splitN = M * HID / 8;
    int wEnd = splitN + HID2 * HID;
    int idx = blockIdx.x * blockDim.x + threadIdx.x;

    if (idx < splitN) {
        const float4* p = reinterpret_cast<const float4*>(z) + (size_t)idx * 2;
        float4 v0 = p[0], v1 = p[1];
        __half h[8];
        h[0] = __float2half_rn(v0.x); h[1] = __float2half_rn(v0.y);
        h[2] = __float2half_rn(v0.z); h[3] = __float2half_rn(v0.w);
        h[4] = __float2half_rn(v1.x); h[5] = __float2half_rn(v1.y);
        h[6] = __float2half_rn(v1.z); h[7] = __float2half_rn(v1.w);
        *reinterpret_cast<uint4*>(&g_Z16[(size_t)idx * 8]) = *reinterpret_cast<uint4*>(h);
    } else if (idx < wEnd) {
        int w = idx - splitN;
        int n = w >> 8;
        int k = w & (HID - 1);
        float v = (n < HID) ? W1[k * HID + n]
                            : W1[(HID + k) * HID + (n - HID)];
        g_Wt[w] = __float2half_rn(v);
    } else if (idx < wEnd + M) {
        g_count[idx - wEnd] = 0;
    }

    if (blockIdx.x == gridDim.x - 1) {
        __shared__ int ok;
        if (threadIdx.x == 0) ok = 1;
        __syncthreads();
        const long long* p = (const long long*)ei;
        int total = 2 * E;
        int samples = total < 4096 ? total : 4096;
        for (int i = threadIdx.x; i < samples; i += blockDim.x) {
            long long v = p[i];
            if (v < 0 || v >= (long long)M) ok = 0;
        }
        __syncthreads();
        if (threadIdx.x == 0) g_idx64_flag = ok;
    }
}

// ---------------------------------------------------------------------------
// Canonicalize indices + histogram on src
// ---------------------------------------------------------------------------
__global__ void convert_hist_kernel(const void* __restrict__ ei, int E, int M) {
    int e = blockIdx.x * blockDim.x + threadIdx.x;
    if (e >= E) return;
    long long s, d;
    if (g_idx64_flag) {
        s = ((const long long*)ei)[e];
        d = ((const long long*)ei)[(size_t)E + e];
    } else {
        s = ((const int*)ei)[e];
        d = ((const int*)ei)[(size_t)E + e];
    }
    s = s < 0 ? 0 : (s >= M ? M - 1 : s);
    d = d < 0 ? 0 : (d >= M ? M - 1 : d);
    *reinterpret_cast<int2*>(&g_EI[2 * e]) = make_int2((int)s, (int)d);
    atomicAdd(&g_count[(int)s], 1);
}

// ---------------------------------------------------------------------------
// One-block exclusive scan over g_count -> g_off (hierarchical warp scan)
// ---------------------------------------------------------------------------
__global__ void scan_kernel(int M) {
    __shared__ int wsum[32];
    __shared__ int running;
    int tid = threadIdx.x, lane = tid & 31, w = tid >> 5;
    if (tid == 0) running = 0;
    __syncthreads();
    int ntiles = (M + 1023) >> 10;
    for (int t = 0; t < ntiles; t++) {
        int i = (t << 10) + tid;
        int v = (i < M) ? g_count[i] : 0;
        int x = v;
#pragma unroll
        for (int off = 1; off < 32; off <<= 1) {
            int y = __shfl_up_sync(0xFFFFFFFFu, x, off);
            if (lane >= off) x += y;
        }
        if (lane == 31) wsum[w] = x;
        __syncthreads();
        if (w == 0) {
            int s = wsum[lane];
#pragma unroll
            for (int off = 1; off < 32; off <<= 1) {
                int y = __shfl_up_sync(0xFFFFFFFFu, s, off);
                if (lane >= off) s += y;
            }
            wsum[lane] = s;
        }
        __syncthreads();
        int base = running + (w > 0 ? wsum[w - 1] : 0);
        if (i < M) g_off[i] = base + x - v;
        __syncthreads();
        if (tid == 0) running += wsum[31];
        __syncthreads();
    }
}

// ---------------------------------------------------------------------------
// Scatter edges into src-sorted order
// ---------------------------------------------------------------------------
__global__ void scatter_kernel(int E) {
    int e = blockIdx.x * blockDim.x + threadIdx.x;
    if (e >= E) return;
    int2 sd = *reinterpret_cast<const int2*>(&g_EI[2 * e]);
    int pos = atomicAdd(&g_off[sd.x], 1);
    g_sorted[pos] = make_int4(sd.x, sd.y, e, 0);
}

// ---------------------------------------------------------------------------
// HMMA GEMM: AB[M,512] = z16[M,256] @ Wt (+ b1 on cols>=256), fp16 output.
// CTA 128m x 128n, 8 warps (warp 64x32), KC=64, 2-stage, 2 CTA/SM.
// ---------------------------------------------------------------------------
#define KC 64
#define OFF_A   0
#define OFF_B   16384
#define STAGE_BYTES 32768
#define SMEM_DYN (2 * STAGE_BYTES)

__global__ __launch_bounds__(256, 2)
void hmma_kernel(const float* __restrict__ b1, int M) {
    extern __shared__ char smem[];
    uint32_t sb = smem_u32(smem);
    int tid = threadIdx.x;
    int wid = tid >> 5;
    int lane = tid & 31;
    int mBase = blockIdx.y * 128;
    int nBase = blockIdx.x * 128;
    int warpM = wid >> 2;
    int warpN = wid & 3;

    float c[4][4][4];
#pragma unroll
    for (int i = 0; i < 4; i++)
#pragma unroll
        for (int j = 0; j < 4; j++)
#pragma unroll
            for (int q = 0; q < 4; q++) c[i][j][q] = 0.f;

    auto load_stage = [&](int s, int kc) {
        uint32_t base = sb + s * STAGE_BYTES;
        int kOff = kc * KC;
#pragma unroll
        for (int i = 0; i < 4; i++) {
            int idx = tid + i * 256;
            int r = idx >> 3;
            int kg = idx & 7;
            uint32_t sw = swz(r, kg * 16);
            int ar = mBase + r;
            ar = ar < M ? ar : M - 1;
            size_t aoff = (size_t)ar * HID + kOff + kg * 8;
            cp16(base + OFF_A + sw, &g_Z16[aoff]);
        }
#pragma unroll
        for (int i = 0; i < 4; i++) {
            int idx = tid + i * 256;
            int r = idx >> 3;
            int kg = idx & 7;
            uint32_t sw = swz(r, kg * 16);
            size_t boff = (size_t)(nBase + r) * HID + kOff + kg * 8;
            cp16(base + OFF_B + sw, &g_Wt[boff]);
        }
        asm volatile("cp.async.commit_group;" ::: "memory");
    };

    load_stage(0, 0);
    load_stage(1, 1);

#pragma unroll 1
    for (int ck = 0; ck < 4; ck++) {
        if (ck < 3) asm volatile("cp.async.wait_group 1;" ::: "memory");
        else        asm volatile("cp.async.wait_group 0;" ::: "memory");
        __syncthreads();

        uint32_t base = sb + (ck & 1) * STAGE_BYTES;
#pragma unroll
        for (int ks = 0; ks < 4; ks++) {
            uint32_t a16[4][4], bf[4][2];
#pragma unroll
            for (int mf = 0; mf < 4; mf++) {
                int r = warpM * 64 + mf * 16 + (lane & 15);
                int kb = ks * 32 + ((lane >> 4) << 4);
                ldsm_x4(a16[mf], base + OFF_A + swz(r, kb));
            }
            // B: two ldsm_x4, each covering 16 n-rows x full k32
#pragma unroll
            for (int p = 0; p < 2; p++) {
                uint32_t btmp[4];
                int g = lane >> 3;                    // 0..3
                int r = warpN * 32 + p * 16 + ((g >> 1) << 3) + (lane & 7);
                int kb = ks * 32 + ((g & 1) << 4);
                ldsm_x4(btmp, base + OFF_B + swz(r, kb));
                bf[p * 2 + 0][0] = btmp[0];
                bf[p * 2 + 0][1] = btmp[1];
                bf[p * 2 + 1][0] = btmp[2];
                bf[p * 2 + 1][1] = btmp[3];
            }
#pragma unroll
            for (int mf = 0; mf < 4; mf++)
#pragma unroll
                for (int nf = 0; nf < 4; nf++)
                    mma_f16(c[mf][nf], a16[mf], bf[nf]);
        }
        __syncthreads();
        if (ck + 2 < 4) load_stage(ck & 1, ck + 2);
    }

    int rowInFrag = lane >> 2;
    int colInFrag = (lane & 3) * 2;
#pragma unroll
    for (int nf = 0; nf < 4; nf++) {
        int col = nBase + warpN * 32 + nf * 8 + colInFrag;
        float bx = 0.f, by = 0.f;
        if (col >= HID) {
            bx = __ldg(&b1[col - HID]);
            by = __ldg(&b1[col - HID + 1]);
        }
#pragma unroll
        for (int mf = 0; mf < 4; mf++) {
            int row0 = mBase + warpM * 64 + mf * 16 + rowInFrag;
            if (row0 < M) {
                __half2 h = __floats2half2_rn(c[mf][nf][0] + bx, c[mf][nf][1] + by);
                *reinterpret_cast<__half2*>(&g_ABh[(size_t)row0 * HID2 + col]) = h;
            }
            int row1 = row0 + 8;
            if (row1 < M) {
                __half2 h = __floats2half2_rn(c[mf][nf][2] + bx, c[mf][nf][3] + by);
                *reinterpret_cast<__half2*>(&g_ABh[(size_t)row1 * HID2 + col]) = h;
            }
        }
    }
}

// ---------------------------------------------------------------------------
// Edge scores: src-sorted contiguous chunks per warp, A-row register reuse.
// ---------------------------------------------------------------------------
#define EDGE_BLOCKS 1184
#define EDGE_THREADS 256

__global__ __launch_bounds__(EDGE_THREADS)
void edge_kernel(const float* __restrict__ W2,
                 const float* __restrict__ b2,
                 float* __restrict__ out,
                 int E) {
    int lane = threadIdx.x & 31;
    int warp = (blockIdx.x * EDGE_THREADS + threadIdx.x) >> 5;
    int nwarps = (gridDim.x * EDGE_THREADS) >> 5;

    const float4* w2v = reinterpret_cast<const float4*>(W2);
    float4 wA = __ldg(&w2v[2 * lane]);
    float4 wB = __ldg(&w2v[2 * lane + 1]);
    float bias = __ldg(b2);
    const __half2 zero2 = __floats2half2_rn(0.f, 0.f);

    int chunk = (E + nwarps - 1) / nwarps;
    int begin = warp * chunk;
    int end = begin + chunk;
    if (end > E) end = E;

    int sprev = -1;
    uint4 av = make_uint4(0, 0, 0, 0);

    for (int e = begin; e < end; e++) {
        int4 t = g_sorted[e];

        if (t.x != sprev) {
            const uint4* Arow = reinterpret_cast<const uint4*>(g_ABh + (size_t)t.x * HID2);
            av = __ldcg(&Arow[lane]);
            sprev = t.x;
        }
        const uint4* Brow = reinterpret_cast<const uint4*>(g_ABh + (size_t)t.y * HID2 + HID);
        uint4 bv = __ldcg(&Brow[lane]);

        const __half2* ah = reinterpret_cast<const __half2*>(&av);
        const __half2* bh = reinterpret_cast<const __half2*>(&bv);

        __half2 r0 = __hmax2(__hadd2(ah[0], bh[0]), zero2);
        __half2 r1 = __hmax2(__hadd2(ah[1], bh[1]), zero2);
        __half2 r2 = __hmax2(__hadd2(ah[2], bh[2]), zero2);
        __half2 r3 = __hmax2(__hadd2(ah[3], bh[3]), zero2);

        float2 f0 = __half22float2(r0);
        float2 f1 = __half22float2(r1);
        float2 f2 = __half22float2(r2);
        float2 f3 = __half22float2(r3);

        float acc = (lane == 0) ? bias : 0.f;
        acc = fmaf(f0.x, wA.x, acc);
        acc = fmaf(f0.y, wA.y, acc);
        acc = fmaf(f1.x, wA.z, acc);
        acc = fmaf(f1.y, wA.w, acc);
        acc = fmaf(f2.x, wB.x, acc);
        acc = fmaf(f2.y, wB.y, acc);
        acc = fmaf(f3.x, wB.z, acc);
        acc = fmaf(f3.y, wB.w, acc);

#pragma unroll
        for (int off = 16; off > 0; off >>= 1)
            acc += __shfl_xor_sync(0xFFFFFFFFu, acc, off);

        if (lane == 0)
            out[t.z] = acc;
    }
}

// ---------------------------------------------------------------------------
// Launch
// ---------------------------------------------------------------------------
extern "C" void kernel_launch(void* const* d_in, const int* in_sizes, int n_in,
                              void* d_out, int out_size) {
    const float* z  = (const float*)d_in[0];
    const void*  ei = d_in[1];
    const float* W1 = (const float*)d_in[2];
    const float* b1 = (const float*)d_in[3];
    const float* W2 = (const float*)d_in[4];
    const float* b2 = (const float*)d_in[5];
    float* out = (float*)d_out;

    int M = in_sizes[0] / HID;   // nodes (50000)
    int E = in_sizes[1] / 2;     // edges (800000)

    int preN = M * HID / 8 + HID2 * HID + M;
    preproc_kernel<<<(preN + 255) / 256, 256>>>(z, W1, ei, M, E);
    convert_hist_kernel<<<(E + 255) / 256, 256>>>(ei, E, M);
    scan_kernel<<<1, 1024>>>(M);
    scatter_kernel<<<(E + 255) / 256, 256>>>(E);

    static int smem_set = 0;
    if (!smem_set) {
        cudaFuncSetAttribute(hmma_kernel,
                             cudaFuncAttributeMaxDynamicSharedMemorySize, SMEM_DYN);
        smem_set = 1;
    }
    dim3 grid(HID2 / 128, (M + 127) / 128);
    hmma_kernel<<<grid, 256, SMEM_DYN>>>(b1, M);

    edge_kernel<<<EDGE_BLOCKS, EDGE_THREADS>>>(W2, b2, out, E);
}

// round 15
// speedup vs baseline: 1.4397x; 1.4397x over previous
#include <cuda_runtime.h>
#include <cuda_bf16.h>
#include <cuda_fp16.h>
#include <cstdint>

#define HID   256
#define HID2  512
#define MAXN  50000
#define MAXE  800000

// Scratch
__device__ __half g_ABh[(size_t)MAXN * HID2];   // fp16 activations (b1 folded)
__device__ __half g_Wt[HID2 * HID];             // [n][k], k-contiguous fp16
__device__ __half g_Z16[(size_t)MAXN * HID];    // z in fp16
__device__ int g_EI[2 * MAXE];                  // interleaved (src,dst) int32
__device__ int g_idx64_flag;

// ---------------------------------------------------------------------------
// helpers
// ---------------------------------------------------------------------------
__device__ __forceinline__ uint32_t smem_u32(const void* p) {
    uint32_t a;
    asm("{ .reg .u64 t; cvta.to.shared.u64 t, %1; cvt.u32.u64 %0, t; }"
        : "=r"(a) : "l"(p));
    return a;
}
__device__ __forceinline__ void cp16(uint32_t s, const void* g) {
    asm volatile("cp.async.cg.shared.global [%0], [%1], 16;" :: "r"(s), "l"(g) : "memory");
}
__device__ __forceinline__ void ldsm_x4(uint32_t* r, uint32_t a) {
    asm volatile("ldmatrix.sync.aligned.m8n8.x4.shared.b16 {%0,%1,%2,%3}, [%4];"
                 : "=r"(r[0]), "=r"(r[1]), "=r"(r[2]), "=r"(r[3]) : "r"(a));
}
__device__ __forceinline__ void mma_f16(float* c, const uint32_t* a, const uint32_t* b) {
    asm volatile("mma.sync.aligned.m16n8k16.row.col.f32.f16.f16.f32 "
                 "{%0,%1,%2,%3}, {%4,%5,%6,%7}, {%8,%9}, {%0,%1,%2,%3};"
                 : "+f"(c[0]), "+f"(c[1]), "+f"(c[2]), "+f"(c[3])
                 : "r"(a[0]), "r"(a[1]), "r"(a[2]), "r"(a[3]), "r"(b[0]), "r"(b[1]));
}
__device__ __forceinline__ uint32_t swz(int r, int kb) {
    return ((uint32_t)(r * 128 + kb)) ^ ((uint32_t)(r & 7) << 4);
}

// ---------------------------------------------------------------------------
// Fused preprocessing: split_z + pack_w + probe (one launch)
// ---------------------------------------------------------------------------
__global__ void preproc_kernel(const float* __restrict__ z,
                               const float* __restrict__ W1,
                               const void* __restrict__ ei,
                               int M, int E) {
    int splitN = M * HID / 8;
    int idx = blockIdx.x * blockDim.x + threadIdx.x;

    if (idx < splitN) {
        const float4* p = reinterpret_cast<const float4*>(z) + (size_t)idx * 2;
        float4 v0 = p[0], v1 = p[1];
        __half h[8];
        h[0] = __float2half_rn(v0.x); h[1] = __float2half_rn(v0.y);
        h[2] = __float2half_rn(v0.z); h[3] = __float2half_rn(v0.w);
        h[4] = __float2half_rn(v1.x); h[5] = __float2half_rn(v1.y);
        h[6] = __float2half_rn(v1.z); h[7] = __float2half_rn(v1.w);
        *reinterpret_cast<uint4*>(&g_Z16[(size_t)idx * 8]) = *reinterpret_cast<uint4*>(h);
    } else if (idx < splitN + HID2 * HID) {
        int w = idx - splitN;
        int n = w >> 8;
        int k = w & (HID - 1);
        float v = (n < HID) ? W1[k * HID + n]
                            : W1[(HID + k) * HID + (n - HID)];
        g_Wt[w] = __float2half_rn(v);
    }

    if (blockIdx.x == gridDim.x - 1) {
        __shared__ int ok;
        if (threadIdx.x == 0) ok = 1;
        __syncthreads();
        const long long* p = (const long long*)ei;
        int total = 2 * E;
        int samples = total < 4096 ? total : 4096;
        for (int i = threadIdx.x; i < samples; i += blockDim.x) {
            long long v = p[i];
            if (v < 0 || v >= (long long)M) ok = 0;
        }
        __syncthreads();
        if (threadIdx.x == 0) g_idx64_flag = ok;
    }
}

// ---------------------------------------------------------------------------
// Canonicalize edge indices -> interleaved clamped int32 pairs (s,d)
// ---------------------------------------------------------------------------
__global__ void convert_idx_kernel(const void* __restrict__ ei, int E, int M) {
    int e = blockIdx.x * blockDim.x + threadIdx.x;
    if (e >= E) return;
    long long s, d;
    if (g_idx64_flag) {
        s = ((const long long*)ei)[e];
        d = ((const long long*)ei)[(size_t)E + e];
    } else {
        s = ((const int*)ei)[e];
        d = ((const int*)ei)[(size_t)E + e];
    }
    s = s < 0 ? 0 : (s >= M ? M - 1 : s);
    d = d < 0 ? 0 : (d >= M ? M - 1 : d);
    *reinterpret_cast<int2*>(&g_EI[2 * e]) = make_int2((int)s, (int)d);
}

// ---------------------------------------------------------------------------
// HMMA GEMM: AB[M,512] = z16[M,256] @ Wt (+ b1 on cols>=256), fp16 output.
// CTA 128m x 128n, 8 warps (warp 64x32), KC=64, 2-stage, 2 CTA/SM.
// ---------------------------------------------------------------------------
#define KC 64
#define OFF_A   0
#define OFF_B   16384
#define STAGE_BYTES 32768
#define SMEM_DYN (2 * STAGE_BYTES)

__global__ __launch_bounds__(256, 2)
void hmma_kernel(const float* __restrict__ b1, int M) {
    extern __shared__ char smem[];
    uint32_t sb = smem_u32(smem);
    int tid = threadIdx.x;
    int wid = tid >> 5;
    int lane = tid & 31;
    int mBase = blockIdx.y * 128;
    int nBase = blockIdx.x * 128;
    int warpM = wid >> 2;
    int warpN = wid & 3;

    float c[4][4][4];
#pragma unroll
    for (int i = 0; i < 4; i++)
#pragma unroll
        for (int j = 0; j < 4; j++)
#pragma unroll
            for (int q = 0; q < 4; q++) c[i][j][q] = 0.f;

    auto load_stage = [&](int s, int kc) {
        uint32_t base = sb + s * STAGE_BYTES;
        int kOff = kc * KC;
#pragma unroll
        for (int i = 0; i < 4; i++) {
            int idx = tid + i * 256;
            int r = idx >> 3;
            int kg = idx & 7;
            uint32_t sw = swz(r, kg * 16);
            int ar = mBase + r;
            ar = ar < M ? ar : M - 1;
            size_t aoff = (size_t)ar * HID + kOff + kg * 8;
            cp16(base + OFF_A + sw, &g_Z16[aoff]);
        }
#pragma unroll
        for (int i = 0; i < 4; i++) {
            int idx = tid + i * 256;
            int r = idx >> 3;
            int kg = idx & 7;
            uint32_t sw = swz(r, kg * 16);
            size_t boff = (size_t)(nBase + r) * HID + kOff + kg * 8;
            cp16(base + OFF_B + sw, &g_Wt[boff]);
        }
        asm volatile("cp.async.commit_group;" ::: "memory");
    };

    load_stage(0, 0);
    load_stage(1, 1);

#pragma unroll 1
    for (int ck = 0; ck < 4; ck++) {
        if (ck < 3) asm volatile("cp.async.wait_group 1;" ::: "memory");
        else        asm volatile("cp.async.wait_group 0;" ::: "memory");
        __syncthreads();

        uint32_t base = sb + (ck & 1) * STAGE_BYTES;
#pragma unroll
        for (int ks = 0; ks < 4; ks++) {
            uint32_t a16[4][4], bf[4][2];
#pragma unroll
            for (int mf = 0; mf < 4; mf++) {
                int r = warpM * 64 + mf * 16 + (lane & 15);
                int kb = ks * 32 + ((lane >> 4) << 4);
                ldsm_x4(a16[mf], base + OFF_A + swz(r, kb));
            }
            // B: two ldsm_x4, each covering 16 n-rows x full k32
#pragma unroll
            for (int p = 0; p < 2; p++) {
                uint32_t btmp[4];
                int g = lane >> 3;                    // 0..3
                int r = warpN * 32 + p * 16 + ((g >> 1) << 3) + (lane & 7);
                int kb = ks * 32 + ((g & 1) << 4);
                ldsm_x4(btmp, base + OFF_B + swz(r, kb));
                bf[p * 2 + 0][0] = btmp[0];
                bf[p * 2 + 0][1] = btmp[1];
                bf[p * 2 + 1][0] = btmp[2];
                bf[p * 2 + 1][1] = btmp[3];
            }
#pragma unroll
            for (int mf = 0; mf < 4; mf++)
#pragma unroll
                for (int nf = 0; nf < 4; nf++)
                    mma_f16(c[mf][nf], a16[mf], bf[nf]);
        }
        __syncthreads();
        if (ck + 2 < 4) load_stage(ck & 1, ck + 2);
    }

    int rowInFrag = lane >> 2;
    int colInFrag = (lane & 3) * 2;
#pragma unroll
    for (int nf = 0; nf < 4; nf++) {
        int col = nBase + warpN * 32 + nf * 8 + colInFrag;
        float bx = 0.f, by = 0.f;
        if (col >= HID) {
            bx = __ldg(&b1[col - HID]);
            by = __ldg(&b1[col - HID + 1]);
        }
#pragma unroll
        for (int mf = 0; mf < 4; mf++) {
            int row0 = mBase + warpM * 64 + mf * 16 + rowInFrag;
            if (row0 < M) {
                __half2 h = __floats2half2_rn(c[mf][nf][0] + bx, c[mf][nf][1] + by);
                *reinterpret_cast<__half2*>(&g_ABh[(size_t)row0 * HID2 + col]) = h;
            }
            int row1 = row0 + 8;
            if (row1 < M) {
                __half2 h = __floats2half2_rn(c[mf][nf][2] + bx, c[mf][nf][3] + by);
                *reinterpret_cast<__half2*>(&g_ABh[(size_t)row1 * HID2 + col]) = h;
            }
        }
    }
}

// ---------------------------------------------------------------------------
// Edge scores: fp16 gather + half2 add/relu, fp32 dot, int2 indices.
// (R13 version — measured 74.1 us; sort-based variants regress.)
// ---------------------------------------------------------------------------
#define EDGE_BLOCKS 1184
#define EDGE_THREADS 256

__global__ __launch_bounds__(EDGE_THREADS)
void edge_kernel(const float* __restrict__ W2,
                 const float* __restrict__ b2,
                 float* __restrict__ out,
                 int E) {
    int lane = threadIdx.x & 31;
    int warp = (blockIdx.x * EDGE_THREADS + threadIdx.x) >> 5;
    int nwarps = (gridDim.x * EDGE_THREADS) >> 5;

    const float4* w2v = reinterpret_cast<const float4*>(W2);
    float4 wA = __ldg(&w2v[2 * lane]);
    float4 wB = __ldg(&w2v[2 * lane + 1]);
    float bias = __ldg(b2);
    const __half2 zero2 = __floats2half2_rn(0.f, 0.f);

    for (int e = warp; e < E; e += nwarps) {
        int2 sd = *reinterpret_cast<const int2*>(&g_EI[2 * e]);

        const uint4* Arow = reinterpret_cast<const uint4*>(g_ABh + (size_t)sd.x * HID2);
        const uint4* Brow = reinterpret_cast<const uint4*>(g_ABh + (size_t)sd.y * HID2 + HID);

        uint4 av = __ldcg(&Arow[lane]);
        uint4 bv = __ldcg(&Brow[lane]);
        const __half2* ah = reinterpret_cast<const __half2*>(&av);
        const __half2* bh = reinterpret_cast<const __half2*>(&bv);

        __half2 r0 = __hmax2(__hadd2(ah[0], bh[0]), zero2);
        __half2 r1 = __hmax2(__hadd2(ah[1], bh[1]), zero2);
        __half2 r2 = __hmax2(__hadd2(ah[2], bh[2]), zero2);
        __half2 r3 = __hmax2(__hadd2(ah[3], bh[3]), zero2);

        float2 f0 = __half22float2(r0);
        float2 f1 = __half22float2(r1);
        float2 f2 = __half22float2(r2);
        float2 f3 = __half22float2(r3);

        float acc = (lane == 0) ? bias : 0.f;
        acc = fmaf(f0.x, wA.x, acc);
        acc = fmaf(f0.y, wA.y, acc);
        acc = fmaf(f1.x, wA.z, acc);
        acc = fmaf(f1.y, wA.w, acc);
        acc = fmaf(f2.x, wB.x, acc);
        acc = fmaf(f2.y, wB.y, acc);
        acc = fmaf(f3.x, wB.z, acc);
        acc = fmaf(f3.y, wB.w, acc);

#pragma unroll
        for (int off = 16; off > 0; off >>= 1)
            acc += __shfl_xor_sync(0xFFFFFFFFu, acc, off);

        if (lane == 0)
            out[e] = acc;
    }
}

// ---------------------------------------------------------------------------
// Launch
// ---------------------------------------------------------------------------
extern "C" void kernel_launch(void* const* d_in, const int* in_sizes, int n_in,
                              void* d_out, int out_size) {
    const float* z  = (const float*)d_in[0];
    const void*  ei = d_in[1];
    const float* W1 = (const float*)d_in[2];
    const float* b1 = (const float*)d_in[3];
    const float* W2 = (const float*)d_in[4];
    const float* b2 = (const float*)d_in[5];
    float* out = (float*)d_out;

    int M = in_sizes[0] / HID;   // nodes (50000)
    int E = in_sizes[1] / 2;     // edges (800000)

    int preN = M * HID / 8 + HID2 * HID;
    preproc_kernel<<<(preN + 255) / 256, 256>>>(z, W1, ei, M, E);
    convert_idx_kernel<<<(E + 255) / 256, 256>>>(ei, E, M);

    static int smem_set = 0;
    if (!smem_set) {
        cudaFuncSetAttribute(hmma_kernel,
                             cudaFuncAttributeMaxDynamicSharedMemorySize, SMEM_DYN);
        smem_set = 1;
    }
    dim3 grid(HID2 / 128, (M + 127) / 128);
    hmma_kernel<<<grid, 256, SMEM_DYN>>>(b1, M);

    edge_kernel<<<EDGE_BLOCKS, EDGE_THREADS>>>(W2, b2, out, E);
}